// round 10
// baseline (speedup 1.0000x reference)
#include <cuda_runtime.h>
#include <cstdint>

// ---------------- problem constants ----------------
#define T_TOK   8192
#define DMODEL  1024
#define NEXP    8
#define DFFN    4096
#define CAPCT   1280            // int(1.25*8192/8), even, >= 4
#define NSLOT   (NEXP*CAPCT)    // 10240

// ---------------- persistent scratch (device globals; no allocs) ----------------
__device__ int   g_top1[T_TOK];
__device__ float g_prob[T_TOK];
__device__ float g_me[NEXP];
__device__ int   g_slot_tok[NSLOT];
__device__ float g_slot_w[NSLOT];
__device__ int   g_cnt_cap[NEXP];
__device__ float g_xd[(size_t)NSLOT * DMODEL];   // dispatched tokens, tf32-rounded
__device__ float g_h[(size_t)NSLOT * DFFN];      // GEMM1 output (gelu'd, tf32-rounded)

// ---------------- small helpers ----------------
__device__ __forceinline__ uint32_t f2tf(float f) {
    uint32_t r; asm("cvt.rna.tf32.f32 %0, %1;" : "=r"(r) : "f"(f)); return r;
}
__device__ __forceinline__ void cp16(uint32_t dst, const void* src) {
    asm volatile("cp.async.cg.shared.global [%0], [%1], 16;" :: "r"(dst), "l"(src));
}
__device__ __forceinline__ void cp_commit() { asm volatile("cp.async.commit_group;"); }
__device__ __forceinline__ void cp_wait1()  { asm volatile("cp.async.wait_group 1;"); }

__device__ __forceinline__ void mma_tf32(float* c, const uint32_t* a, uint32_t b0, uint32_t b1) {
    asm volatile(
        "mma.sync.aligned.m16n8k8.row.col.f32.tf32.tf32.f32 "
        "{%0,%1,%2,%3},{%4,%5,%6,%7},{%8,%9},{%0,%1,%2,%3};"
        : "+f"(c[0]), "+f"(c[1]), "+f"(c[2]), "+f"(c[3])
        : "r"(a[0]), "r"(a[1]), "r"(a[2]), "r"(a[3]), "r"(b0), "r"(b1));
}

__device__ __forceinline__ float gelu_f(float x) {
    float u = 0.7978845608028654f * (x + 0.044715f * x * x * x);
    float e = __expf(2.f * u);
    float t = 1.f - 2.f / (e + 1.f);
    return 0.5f * x * (1.f + t);
}

// ---------------- kernel 0: zero output + me accumulators ----------------
__global__ void zero_kernel(float* __restrict__ out, int n) {
    int idx = blockIdx.x * blockDim.x + threadIdx.x;
    int stride = gridDim.x * blockDim.x;
    for (int i = idx; i < n; i += stride) out[i] = 0.f;
    if (blockIdx.x == 0 && threadIdx.x < NEXP) g_me[threadIdx.x] = 0.f;
}

// ---------------- kernel 1: gating (1 warp per token) ----------------
__global__ __launch_bounds__(256) void gating_kernel(
    const float* __restrict__ tokens, const float* __restrict__ gw) {
    __shared__ float4 sgw[NEXP * 256];
    __shared__ float sme[NEXP];
    int tid = threadIdx.x;
    const float4* gw4 = (const float4*)gw;
    for (int i = tid; i < NEXP * 256; i += 256) sgw[i] = gw4[i];
    if (tid < NEXP) sme[tid] = 0.f;
    __syncthreads();

    int warp = tid >> 5, lane = tid & 31;
    int t = blockIdx.x * 8 + warp;
    const float4* tok = (const float4*)(tokens + (size_t)t * DMODEL);

    float acc[NEXP];
#pragma unroll
    for (int e = 0; e < NEXP; e++) acc[e] = 0.f;
#pragma unroll
    for (int j = 0; j < 8; j++) {
        float4 x = tok[lane + 32 * j];
#pragma unroll
        for (int e = 0; e < NEXP; e++) {
            float4 w = sgw[e * 256 + lane + 32 * j];
            acc[e] += x.x * w.x + x.y * w.y + x.z * w.z + x.w * w.w;
        }
    }
#pragma unroll
    for (int off = 16; off; off >>= 1)
#pragma unroll
        for (int e = 0; e < NEXP; e++)
            acc[e] += __shfl_xor_sync(0xffffffffu, acc[e], off);

    if (lane == 0) {
        float mx = acc[0]; int am = 0;
#pragma unroll
        for (int e = 1; e < NEXP; e++) if (acc[e] > mx) { mx = acc[e]; am = e; }
        float p[NEXP], s = 0.f;
#pragma unroll
        for (int e = 0; e < NEXP; e++) { p[e] = expf(acc[e] - mx); s += p[e]; }
        float inv = 1.f / s;
        g_top1[t] = am;
        g_prob[t] = p[am] * inv;
#pragma unroll
        for (int e = 0; e < NEXP; e++) atomicAdd(&sme[e], p[e] * inv);
    }
    __syncthreads();
    if (tid < NEXP) atomicAdd(&g_me[tid], sme[tid]);
}

// ---------------- kernel 2: routing scan (single block, exact cumsum order) ----------------
__global__ __launch_bounds__(1024) void scan_kernel(float* __restrict__ out, int out_size) {
    __shared__ int sh_wc[NEXP][32];
    __shared__ int sh_base[NEXP];
    __shared__ int sh_tot[NEXP];
    int tid = threadIdx.x, warp = tid >> 5, lane = tid & 31;
    unsigned ltmask = (1u << lane) - 1u;
    if (tid < NEXP) sh_base[tid] = 0;
    __syncthreads();

    for (int tile = 0; tile < T_TOK / 1024; tile++) {
        int t = tile * 1024 + tid;
        int e = g_top1[t];
        int rank_w = 0;
#pragma unroll
        for (int e8 = 0; e8 < NEXP; e8++) {
            unsigned m = __ballot_sync(0xffffffffu, e == e8);
            if (e == e8) rank_w = __popc(m & ltmask);
            if (lane == 0) sh_wc[e8][warp] = __popc(m);
        }
        __syncthreads();
        if (warp < NEXP) {
            int c = sh_wc[warp][lane];
            int s = c;
#pragma unroll
            for (int off = 1; off < 32; off <<= 1) {
                int v = __shfl_up_sync(0xffffffffu, s, off);
                if (lane >= off) s += v;
            }
            sh_wc[warp][lane] = s - c;
            if (lane == 31) sh_tot[warp] = s;
        }
        __syncthreads();
        int rank = sh_base[e] + sh_wc[e][warp] + rank_w;
        if (rank < CAPCT) {
            int slot = e * CAPCT + rank;
            g_slot_tok[slot] = t;
            g_slot_w[slot] = g_prob[t];
        }
        __syncthreads();
        if (tid < NEXP) sh_base[tid] += sh_tot[tid];
        __syncthreads();
    }

    if (tid < NEXP) g_cnt_cap[tid] = min(sh_base[tid], CAPCT);
    __syncthreads();
    for (int i = tid; i < NSLOT; i += 1024) {
        int e = i / CAPCT, r = i - e * CAPCT;
        if (r >= min(sh_base[e], CAPCT)) { g_slot_tok[i] = -1; g_slot_w[i] = 0.f; }
    }
    if (tid == 0 && out_size > T_TOK * DMODEL) {
        float la = 0.f;
        const float invT = 1.f / (float)T_TOK;
#pragma unroll
        for (int e = 0; e < NEXP; e++)
            la += (g_me[e] * invT) * ((float)sh_base[e] * invT);
        out[T_TOK * DMODEL] = (float)NEXP * la;
    }
}

// ---------------- kernel 3: dispatch gather (tf32-rounded) ----------------
__global__ __launch_bounds__(256) void dispatch_kernel(const float* __restrict__ tokens) {
    int slot = blockIdx.x;
    int tok = g_slot_tok[slot];
    uint4* dst = (uint4*)(g_xd + (size_t)slot * DMODEL);
    if (tok < 0) {
        dst[threadIdx.x] = make_uint4(0u, 0u, 0u, 0u);
    } else {
        const float4* src = (const float4*)(tokens + (size_t)tok * DMODEL);
        float4 v = src[threadIdx.x];
        dst[threadIdx.x] = make_uint4(f2tf(v.x), f2tf(v.y), f2tf(v.z), f2tf(v.w));
    }
}

// ---- GEMM: 128x128x16 tiles, tf32 mma.sync, 3-stage cp.async, 3 CTAs/SM ----
#define BM 128
#define BN 128
#define BK 16
#define AST 20                   // padded A row stride (floats)
#define BST 136                  // padded B row stride (floats)
#define SA_STAGE (BM*AST)        // 2560 floats
#define SB_STAGE (BK*BST)        // 2176 floats
#define GSTAGES 3
#define SMEM_BYTES ((GSTAGES*(SA_STAGE+SB_STAGE))*4)   // 56832 B

// MODE 1: h = gelu(g_xd @ w1 + b1)         (K=1024, N=4096)
// MODE 2: out[token] = w * (g_h @ w2 + b2) (K=4096, N=1024), scatter
template <int MODE>
__global__ __launch_bounds__(256, 3) void ffn_gemm(
    const float* __restrict__ Wbase,
    const float* __restrict__ biasBase, float* __restrict__ Obase) {
    constexpr int N = (MODE == 1) ? DFFN : DMODEL;
    constexpr int K = (MODE == 1) ? DMODEL : DFFN;
    constexpr int KT = K / BK;

    const float* Abase = (MODE == 1) ? g_xd : g_h;   // device-side symbol ref
    constexpr int AROWSTRIDE = (MODE == 1) ? DMODEL : DFFN;

    const int e = blockIdx.z;
    const int mtile = blockIdx.y;
    const int ntile = blockIdx.x;
    if (mtile * BM >= g_cnt_cap[e]) return;

    extern __shared__ __align__(16) float smem[];
    float* sA = smem;
    float* sB = smem + GSTAGES * SA_STAGE;
    uint32_t sA32 = (uint32_t)__cvta_generic_to_shared(sA);
    uint32_t sB32 = (uint32_t)__cvta_generic_to_shared(sB);

    const int tid = threadIdx.x;
    const int lane = tid & 31, warp = tid >> 5;
    const int wm = warp >> 1, wn = warp & 1;      // 4x2 warp grid: 32x64 per warp
    const int g = lane >> 2, tig = lane & 3;

    const float* W = Wbase + (size_t)e * K * N;
    const float* bias = biasBase + (size_t)e * N;
    const int slot0 = e * CAPCT + mtile * BM;

    // per-thread copy assignments (fixed rows across all k-tiles)
    const float* asrc[2]; uint32_t adst[2];
    const int akc = tid & 3;
#pragma unroll
    for (int i = 0; i < 2; i++) {
        int arow = (tid >> 2) + i * 64;
        asrc[i] = Abase + (size_t)(slot0 + arow) * AROWSTRIDE + akc * 4;
        adst[i] = sA32 + (arow * AST + akc * 4) * 4;
    }
    const float* bsrc[2]; uint32_t bdst[2];
    const int bc = tid & 31;
#pragma unroll
    for (int i = 0; i < 2; i++) {
        int brow = (tid >> 5) + i * 8;
        bsrc[i] = W + (size_t)brow * N + ntile * BN + bc * 4;
        bdst[i] = sB32 + (brow * BST + bc * 4) * 4;
    }

    auto issue = [&](int kt, int stage) {
        uint32_t ao = stage * SA_STAGE * 4;
        uint32_t bo = stage * SB_STAGE * 4;
        size_t kA = (size_t)kt * BK;
        size_t kB = (size_t)kt * BK * N;
        cp16(adst[0] + ao, asrc[0] + kA);
        cp16(adst[1] + ao, asrc[1] + kA);
        cp16(bdst[0] + bo, bsrc[0] + kB);
        cp16(bdst[1] + bo, bsrc[1] + kB);
    };

    float acc[2][8][4];
#pragma unroll
    for (int mt = 0; mt < 2; mt++)
#pragma unroll
        for (int nt = 0; nt < 8; nt++)
#pragma unroll
            for (int c = 0; c < 4; c++) acc[mt][nt][c] = 0.f;

    issue(0, 0); cp_commit();
    issue(1, 1); cp_commit();

    int cur = 0, nxst = 2;
    for (int kt = 0; kt < KT; kt++) {
        cp_wait1();
        __syncthreads();
        int nx = kt + 2;
        if (nx < KT) issue(nx, nxst);
        cp_commit();

        const uint32_t* As = (const uint32_t*)(sA + cur * SA_STAGE);
        const uint32_t* Bs = (const uint32_t*)(sB + cur * SB_STAGE);
#pragma unroll
        for (int ks = 0; ks < 2; ks++) {
            uint32_t af[2][4];
#pragma unroll
            for (int mt = 0; mt < 2; mt++) {
                const uint32_t* p = As + (wm * 32 + mt * 16 + g) * AST + ks * 8 + tig;
                af[mt][0] = p[0];
                af[mt][1] = p[8 * AST];
                af[mt][2] = p[4];
                af[mt][3] = p[8 * AST + 4];
            }
            // B loaded per-nt (2 live regs) to fit the 85-reg budget for 3 CTAs/SM
#pragma unroll
            for (int nt = 0; nt < 8; nt++) {
                const uint32_t* p = Bs + (ks * 8 + tig) * BST + wn * 64 + nt * 8 + g;
                uint32_t b0 = p[0];
                uint32_t b1 = p[4 * BST];
                mma_tf32(acc[0][nt], af[0], b0, b1);
                mma_tf32(acc[1][nt], af[1], b0, b1);
            }
        }
        cur = (cur == GSTAGES - 1) ? 0 : cur + 1;
        nxst = (nxst == GSTAGES - 1) ? 0 : nxst + 1;
    }

    // ---- epilogue ----
    if (MODE == 1) {
#pragma unroll
        for (int mt = 0; mt < 2; mt++)
#pragma unroll
            for (int half = 0; half < 2; half++) {
                int rloc = wm * 32 + mt * 16 + g + half * 8;
                float* hrow = g_h + (size_t)(slot0 + rloc) * DFFN;
#pragma unroll
                for (int nt = 0; nt < 8; nt++) {
                    int col = ntile * BN + wn * 64 + nt * 8 + 2 * tig;
                    float2 bb = *(const float2*)(bias + col);
                    float v0 = gelu_f(acc[mt][nt][half * 2 + 0] + bb.x);
                    float v1 = gelu_f(acc[mt][nt][half * 2 + 1] + bb.y);
                    // pre-round h to tf32 so GEMM2's consumer needs no cvt
                    *(uint2*)(hrow + col) = make_uint2(f2tf(v0), f2tf(v1));
                }
            }
    } else {
#pragma unroll
        for (int mt = 0; mt < 2; mt++)
#pragma unroll
            for (int half = 0; half < 2; half++) {
                int rloc = wm * 32 + mt * 16 + g + half * 8;
                int slot = slot0 + rloc;
                int tok = g_slot_tok[slot];
                if (tok >= 0) {
                    float w = g_slot_w[slot];
                    float* orow = Obase + (size_t)tok * DMODEL;
#pragma unroll
                    for (int nt = 0; nt < 8; nt++) {
                        int col = ntile * BN + wn * 64 + nt * 8 + 2 * tig;
                        float2 bb = *(const float2*)(bias + col);
                        float v0 = (acc[mt][nt][half * 2 + 0] + bb.x) * w;
                        float v1 = (acc[mt][nt][half * 2 + 1] + bb.y) * w;
                        *(float2*)(orow + col) = make_float2(v0, v1);
                    }
                }
            }
    }
}

// ---------------- launch ----------------
extern "C" void kernel_launch(void* const* d_in, const int* in_sizes, int n_in,
                              void* d_out, int out_size) {
    const float* inputs = (const float*)d_in[0];
    const float* gatew  = (const float*)d_in[1];
    const float* w1     = (const float*)d_in[2];
    const float* b1     = (const float*)d_in[3];
    const float* w2     = (const float*)d_in[4];
    const float* b2     = (const float*)d_in[5];
    float* out = (float*)d_out;

    cudaFuncSetAttribute(ffn_gemm<1>, cudaFuncAttributeMaxDynamicSharedMemorySize, SMEM_BYTES);
    cudaFuncSetAttribute(ffn_gemm<2>, cudaFuncAttributeMaxDynamicSharedMemorySize, SMEM_BYTES);

    zero_kernel<<<2048, 256>>>(out, out_size);
    gating_kernel<<<T_TOK / 8, 256>>>(inputs, gatew);
    scan_kernel<<<1, 1024>>>(out, out_size);
    dispatch_kernel<<<NSLOT, 256>>>(inputs);
    ffn_gemm<1><<<dim3(DFFN / BN, CAPCT / BM, NEXP), 256, SMEM_BYTES>>>(w1, b1, nullptr);
    ffn_gemm<2><<<dim3(DMODEL / BN, CAPCT / BM, NEXP), 256, SMEM_BYTES>>>(w2, b2, out);
}

// round 11
// speedup vs baseline: 1.2706x; 1.2706x over previous
#include <cuda_runtime.h>
#include <cstdint>

// ---------------- problem constants ----------------
#define T_TOK   8192
#define DMODEL  1024
#define NEXP    8
#define DFFN    4096
#define CAPCT   1280            // int(1.25*8192/8), even, >= 4
#define NSLOT   (NEXP*CAPCT)    // 10240

// ---------------- persistent scratch (device globals; no allocs) ----------------
__device__ int   g_top1[T_TOK];
__device__ float g_prob[T_TOK];
__device__ float g_me[NEXP];
__device__ int   g_slot_tok[NSLOT];
__device__ float g_slot_w[NSLOT];
__device__ int   g_cnt_cap[NEXP];
__device__ float g_xd[(size_t)NSLOT * DMODEL];   // dispatched tokens, tf32-rounded
__device__ float g_h[(size_t)NSLOT * DFFN];      // GEMM1 output (gelu'd, tf32-rounded)

// ---------------- small helpers ----------------
__device__ __forceinline__ uint32_t f2tf(float f) {
    uint32_t r; asm("cvt.rna.tf32.f32 %0, %1;" : "=r"(r) : "f"(f)); return r;
}
__device__ __forceinline__ void cp16(uint32_t dst, const void* src) {
    asm volatile("cp.async.cg.shared.global [%0], [%1], 16;" :: "r"(dst), "l"(src));
}
__device__ __forceinline__ void cp_commit() { asm volatile("cp.async.commit_group;"); }
__device__ __forceinline__ void cp_wait1()  { asm volatile("cp.async.wait_group 1;"); }

__device__ __forceinline__ void mma_tf32(float* c, const uint32_t* a, uint32_t b0, uint32_t b1) {
    asm volatile(
        "mma.sync.aligned.m16n8k8.row.col.f32.tf32.tf32.f32 "
        "{%0,%1,%2,%3},{%4,%5,%6,%7},{%8,%9},{%0,%1,%2,%3};"
        : "+f"(c[0]), "+f"(c[1]), "+f"(c[2]), "+f"(c[3])
        : "r"(a[0]), "r"(a[1]), "r"(a[2]), "r"(a[3]), "r"(b0), "r"(b1));
}

__device__ __forceinline__ float gelu_f(float x) {
    float u = 0.7978845608028654f * (x + 0.044715f * x * x * x);
    float e = __expf(2.f * u);
    float t = 1.f - 2.f / (e + 1.f);
    return 0.5f * x * (1.f + t);
}

// ---------------- kernel 0: zero output + me accumulators ----------------
__global__ void zero_kernel(float* __restrict__ out, int n) {
    int idx = blockIdx.x * blockDim.x + threadIdx.x;
    int stride = gridDim.x * blockDim.x;
    for (int i = idx; i < n; i += stride) out[i] = 0.f;
    if (blockIdx.x == 0 && threadIdx.x < NEXP) g_me[threadIdx.x] = 0.f;
}

// ---------------- kernel 1: gating (1 warp per token) ----------------
__global__ __launch_bounds__(256) void gating_kernel(
    const float* __restrict__ tokens, const float* __restrict__ gw) {
    __shared__ float4 sgw[NEXP * 256];
    __shared__ float sme[NEXP];
    int tid = threadIdx.x;
    const float4* gw4 = (const float4*)gw;
    for (int i = tid; i < NEXP * 256; i += 256) sgw[i] = gw4[i];
    if (tid < NEXP) sme[tid] = 0.f;
    __syncthreads();

    int warp = tid >> 5, lane = tid & 31;
    int t = blockIdx.x * 8 + warp;
    const float4* tok = (const float4*)(tokens + (size_t)t * DMODEL);

    float acc[NEXP];
#pragma unroll
    for (int e = 0; e < NEXP; e++) acc[e] = 0.f;
#pragma unroll
    for (int j = 0; j < 8; j++) {
        float4 x = tok[lane + 32 * j];
#pragma unroll
        for (int e = 0; e < NEXP; e++) {
            float4 w = sgw[e * 256 + lane + 32 * j];
            acc[e] += x.x * w.x + x.y * w.y + x.z * w.z + x.w * w.w;
        }
    }
#pragma unroll
    for (int off = 16; off; off >>= 1)
#pragma unroll
        for (int e = 0; e < NEXP; e++)
            acc[e] += __shfl_xor_sync(0xffffffffu, acc[e], off);

    if (lane == 0) {
        float mx = acc[0]; int am = 0;
#pragma unroll
        for (int e = 1; e < NEXP; e++) if (acc[e] > mx) { mx = acc[e]; am = e; }
        float p[NEXP], s = 0.f;
#pragma unroll
        for (int e = 0; e < NEXP; e++) { p[e] = expf(acc[e] - mx); s += p[e]; }
        float inv = 1.f / s;
        g_top1[t] = am;
        g_prob[t] = p[am] * inv;
#pragma unroll
        for (int e = 0; e < NEXP; e++) atomicAdd(&sme[e], p[e] * inv);
    }
    __syncthreads();
    if (tid < NEXP) atomicAdd(&g_me[tid], sme[tid]);
}

// ---------------- kernel 2: routing scan (single block, exact cumsum order) ----------------
__global__ __launch_bounds__(1024) void scan_kernel(float* __restrict__ out, int out_size) {
    __shared__ int sh_wc[NEXP][32];
    __shared__ int sh_base[NEXP];
    __shared__ int sh_tot[NEXP];
    int tid = threadIdx.x, warp = tid >> 5, lane = tid & 31;
    unsigned ltmask = (1u << lane) - 1u;
    if (tid < NEXP) sh_base[tid] = 0;
    __syncthreads();

    for (int tile = 0; tile < T_TOK / 1024; tile++) {
        int t = tile * 1024 + tid;
        int e = g_top1[t];
        int rank_w = 0;
#pragma unroll
        for (int e8 = 0; e8 < NEXP; e8++) {
            unsigned m = __ballot_sync(0xffffffffu, e == e8);
            if (e == e8) rank_w = __popc(m & ltmask);
            if (lane == 0) sh_wc[e8][warp] = __popc(m);
        }
        __syncthreads();
        if (warp < NEXP) {
            int c = sh_wc[warp][lane];
            int s = c;
#pragma unroll
            for (int off = 1; off < 32; off <<= 1) {
                int v = __shfl_up_sync(0xffffffffu, s, off);
                if (lane >= off) s += v;
            }
            sh_wc[warp][lane] = s - c;
            if (lane == 31) sh_tot[warp] = s;
        }
        __syncthreads();
        int rank = sh_base[e] + sh_wc[e][warp] + rank_w;
        if (rank < CAPCT) {
            int slot = e * CAPCT + rank;
            g_slot_tok[slot] = t;
            g_slot_w[slot] = g_prob[t];
        }
        __syncthreads();
        if (tid < NEXP) sh_base[tid] += sh_tot[tid];
        __syncthreads();
    }

    if (tid < NEXP) g_cnt_cap[tid] = min(sh_base[tid], CAPCT);
    __syncthreads();
    for (int i = tid; i < NSLOT; i += 1024) {
        int e = i / CAPCT, r = i - e * CAPCT;
        if (r >= min(sh_base[e], CAPCT)) { g_slot_tok[i] = -1; g_slot_w[i] = 0.f; }
    }
    if (tid == 0 && out_size > T_TOK * DMODEL) {
        float la = 0.f;
        const float invT = 1.f / (float)T_TOK;
#pragma unroll
        for (int e = 0; e < NEXP; e++)
            la += (g_me[e] * invT) * ((float)sh_base[e] * invT);
        out[T_TOK * DMODEL] = (float)NEXP * la;
    }
}

// ---------------- kernel 3: dispatch gather (tf32-rounded) ----------------
__global__ __launch_bounds__(256) void dispatch_kernel(const float* __restrict__ tokens) {
    int slot = blockIdx.x;
    int tok = g_slot_tok[slot];
    uint4* dst = (uint4*)(g_xd + (size_t)slot * DMODEL);
    if (tok < 0) {
        dst[threadIdx.x] = make_uint4(0u, 0u, 0u, 0u);
    } else {
        const float4* src = (const float4*)(tokens + (size_t)tok * DMODEL);
        float4 v = src[threadIdx.x];
        dst[threadIdx.x] = make_uint4(f2tf(v.x), f2tf(v.y), f2tf(v.z), f2tf(v.w));
    }
}

// ---- GEMM: 64x128x16 CTA tile, 32x32 warp tile (2x4 warps), 3-stage cp.async ----
// Small acc footprint (32 regs) -> 3 CTAs/SM without spills -> 24 warps/SM.
#define BM 64
#define BN 128
#define BK 16
#define AST 20                   // padded A row stride (floats)
#define BST 136                  // padded B row stride (floats)
#define SA_STAGE (BM*AST)        // 1280 floats
#define SB_STAGE (BK*BST)        // 2176 floats
#define GSTAGES 3                // 41472 B static shared

// MODE 1: h = gelu(g_xd @ w1 + b1)         (K=1024, N=4096)
// MODE 2: out[token] = w * (g_h @ w2 + b2) (K=4096, N=1024), scatter
template <int MODE>
__global__ __launch_bounds__(256, 3) void ffn_gemm(
    const float* __restrict__ Wbase,
    const float* __restrict__ biasBase, float* __restrict__ Obase) {
    constexpr int N = (MODE == 1) ? DFFN : DMODEL;
    constexpr int K = (MODE == 1) ? DMODEL : DFFN;
    constexpr int KT = K / BK;

    const float* Abase = (MODE == 1) ? g_xd : g_h;   // device-side symbol ref
    constexpr int AROWSTRIDE = (MODE == 1) ? DMODEL : DFFN;

    const int e = blockIdx.z;
    const int mtile = blockIdx.y;
    const int ntile = blockIdx.x;
    if (mtile * BM >= g_cnt_cap[e]) return;

    __shared__ __align__(16) float sA[GSTAGES][SA_STAGE];
    __shared__ __align__(16) float sB[GSTAGES][SB_STAGE];
    uint32_t sA32 = (uint32_t)__cvta_generic_to_shared(&sA[0][0]);
    uint32_t sB32 = (uint32_t)__cvta_generic_to_shared(&sB[0][0]);

    const int tid = threadIdx.x;
    const int lane = tid & 31, warp = tid >> 5;
    const int wm = warp >> 2, wn = warp & 3;      // 2x4 warp grid: 32x32 per warp
    const int g = lane >> 2, tig = lane & 3;

    const float* W = Wbase + (size_t)e * K * N;
    const float* bias = biasBase + (size_t)e * N;
    const int slot0 = e * CAPCT + mtile * BM;

    // ---- producer assignments ----
    // A: 64 rows x 4 float4 -> 1 cp16/thread. row = tid>>2, kc = tid&3.
    const int akc = tid & 3;
    const int arow = tid >> 2;
    const float* asrc = Abase + (size_t)(slot0 + arow) * AROWSTRIDE + akc * 4;
    const uint32_t adst = sA32 + (arow * AST + akc * 4) * 4;
    // B: 16 rows x 32 float4 -> 2 cp16/thread. rows tid>>5 and +8, col = tid&31.
    const int bc = tid & 31;
    const float* bsrc[2]; uint32_t bdst[2];
#pragma unroll
    for (int i = 0; i < 2; i++) {
        int brow = (tid >> 5) + i * 8;
        bsrc[i] = W + (size_t)brow * N + ntile * BN + bc * 4;
        bdst[i] = sB32 + (brow * BST + bc * 4) * 4;
    }

    auto issue = [&](int kt, int stage) {
        uint32_t ao = stage * (SA_STAGE * 4);
        uint32_t bo = stage * (SB_STAGE * 4);
        size_t kA = (size_t)kt * BK;
        size_t kB = (size_t)kt * BK * N;
        cp16(adst + ao, asrc + kA);
        cp16(bdst[0] + bo, bsrc[0] + kB);
        cp16(bdst[1] + bo, bsrc[1] + kB);
    };

    float acc[2][4][4];
#pragma unroll
    for (int mt = 0; mt < 2; mt++)
#pragma unroll
        for (int nt = 0; nt < 4; nt++)
#pragma unroll
            for (int c = 0; c < 4; c++) acc[mt][nt][c] = 0.f;

    issue(0, 0); cp_commit();
    issue(1, 1); cp_commit();

    int cur = 0, nxst = 2;
    for (int kt = 0; kt < KT; kt++) {
        cp_wait1();
        __syncthreads();
        int nx = kt + 2;
        if (nx < KT) issue(nx, nxst);
        cp_commit();

        const uint32_t* As = (const uint32_t*)&sA[cur][0];
        const uint32_t* Bs = (const uint32_t*)&sB[cur][0];
#pragma unroll
        for (int ks = 0; ks < 2; ks++) {
            uint32_t af[2][4];
#pragma unroll
            for (int mt = 0; mt < 2; mt++) {
                const uint32_t* p = As + (wm * 32 + mt * 16 + g) * AST + ks * 8 + tig;
                af[mt][0] = p[0];
                af[mt][1] = p[8 * AST];
                af[mt][2] = p[4];
                af[mt][3] = p[8 * AST + 4];
            }
#pragma unroll
            for (int nt = 0; nt < 4; nt++) {
                const uint32_t* p = Bs + (ks * 8 + tig) * BST + wn * 32 + nt * 8 + g;
                uint32_t b0 = p[0];
                uint32_t b1 = p[4 * BST];
                mma_tf32(acc[0][nt], af[0], b0, b1);
                mma_tf32(acc[1][nt], af[1], b0, b1);
            }
        }
        cur = (cur == GSTAGES - 1) ? 0 : cur + 1;
        nxst = (nxst == GSTAGES - 1) ? 0 : nxst + 1;
    }

    // ---- epilogue ----
    if (MODE == 1) {
#pragma unroll
        for (int mt = 0; mt < 2; mt++)
#pragma unroll
            for (int half = 0; half < 2; half++) {
                int rloc = wm * 32 + mt * 16 + g + half * 8;
                float* hrow = g_h + (size_t)(slot0 + rloc) * DFFN;
#pragma unroll
                for (int nt = 0; nt < 4; nt++) {
                    int col = ntile * BN + wn * 32 + nt * 8 + 2 * tig;
                    float2 bb = *(const float2*)(bias + col);
                    float v0 = gelu_f(acc[mt][nt][half * 2 + 0] + bb.x);
                    float v1 = gelu_f(acc[mt][nt][half * 2 + 1] + bb.y);
                    // pre-round h to tf32 so GEMM2's consumer needs no cvt
                    *(uint2*)(hrow + col) = make_uint2(f2tf(v0), f2tf(v1));
                }
            }
    } else {
#pragma unroll
        for (int mt = 0; mt < 2; mt++)
#pragma unroll
            for (int half = 0; half < 2; half++) {
                int rloc = wm * 32 + mt * 16 + g + half * 8;
                int slot = slot0 + rloc;
                int tok = g_slot_tok[slot];
                if (tok >= 0) {
                    float w = g_slot_w[slot];
                    float* orow = Obase + (size_t)tok * DMODEL;
#pragma unroll
                    for (int nt = 0; nt < 4; nt++) {
                        int col = ntile * BN + wn * 32 + nt * 8 + 2 * tig;
                        float2 bb = *(const float2*)(bias + col);
                        float v0 = (acc[mt][nt][half * 2 + 0] + bb.x) * w;
                        float v1 = (acc[mt][nt][half * 2 + 1] + bb.y) * w;
                        *(float2*)(orow + col) = make_float2(v0, v1);
                    }
                }
            }
    }
}

// ---------------- launch ----------------
extern "C" void kernel_launch(void* const* d_in, const int* in_sizes, int n_in,
                              void* d_out, int out_size) {
    const float* inputs = (const float*)d_in[0];
    const float* gatew  = (const float*)d_in[1];
    const float* w1     = (const float*)d_in[2];
    const float* b1     = (const float*)d_in[3];
    const float* w2     = (const float*)d_in[4];
    const float* b2     = (const float*)d_in[5];
    float* out = (float*)d_out;

    zero_kernel<<<2048, 256>>>(out, out_size);
    gating_kernel<<<T_TOK / 8, 256>>>(inputs, gatew);
    scan_kernel<<<1, 1024>>>(out, out_size);
    dispatch_kernel<<<NSLOT, 256>>>(inputs);
    ffn_gemm<1><<<dim3(DFFN / BN, CAPCT / BM, NEXP), 256>>>(w1, b1, nullptr);
    ffn_gemm<2><<<dim3(DMODEL / BN, CAPCT / BM, NEXP), 256>>>(w2, b2, out);
}